// round 14
// baseline (speedup 1.0000x reference)
#include <cuda_runtime.h>
#include <math.h>

// ---------------- problem constants ----------------
#define BB 2
#define CC 32
#define HID 16
#define K144 144
#define M4096 4096

typedef unsigned long long ull;

// ---------------- packed f32x2 helpers ----------------
__device__ __forceinline__ ull pk(float lo, float hi) {
    ull r; asm("mov.b64 %0, {%1,%2};" : "=l"(r) : "f"(lo), "f"(hi)); return r;
}
__device__ __forceinline__ ull splat(float v) { return pk(v, v); }
__device__ __forceinline__ float2 upk(ull v) {
    float2 r; asm("mov.b64 {%0,%1}, %2;" : "=f"(r.x), "=f"(r.y) : "l"(v)); return r;
}
__device__ __forceinline__ ull ffma2(ull a, ull b, ull c) {
    ull d; asm("fma.rn.f32x2 %0, %1, %2, %3;" : "=l"(d) : "l"(a), "l"(b), "l"(c)); return d;
}
__device__ __forceinline__ ull add2(ull a, ull b) {
    ull d; asm("add.rn.f32x2 %0, %1, %2;" : "=l"(d) : "l"(a), "l"(b)); return d;
}

// ---------------- device scratch ----------------
__device__ __align__(16) float2 g_S2[BB*CC*64*256];
__device__ __align__(16) float2 g_XS[BB*CC*M4096];
__device__ __align__(16) float2 g_C1P[BB*CC*8*K144];
__device__ __align__(16) float2 g_C3[BB*HID*K144];
__device__ __align__(16) float2 g_T2[BB*64*64*256];
__device__ int    g_shell[M4096];
__device__ __align__(16) float g_YW[M4096*9];      // unscaled, [m][l]
__device__ __align__(16) float g_YWT[9*M4096];     // scaled, [l][m]
__device__ __align__(16) float g_YWsT[9*M4096];    // scaled, [l][sorted p]
__device__ int    g_sorted[M4096];
__device__ int    g_off[17];
__device__ float2 g_TW[64];
__device__ float2 g_WC[HID*CC];
__device__ float2 g_BC[HID];

// ---------------- K0a: mode tables (blocks 0..31) + W1-fold (block 32) ----------------
__global__ void k0a_init(const float* __restrict__ wfr, const float* __restrict__ wfi,
                         const float* __restrict__ bfr, const float* __restrict__ bfi,
                         const float* __restrict__ w1r, const float* __restrict__ w1i,
                         const float* __restrict__ b1r, const float* __restrict__ b1i) {
    if (blockIdx.x < 32) {
        int m = blockIdx.x * 128 + threadIdx.x;
        int ix = m >> 8, iy = (m >> 4) & 15, iz = m & 15;
        int fx = ix < 8 ? ix : ix - 16;
        int fy = iy < 8 ? iy : iy - 16;
        int fz = iz < 8 ? iz : iz - 16;
        int k2 = fx*fx + fy*fy + fz*fz;
        float rmax  = __fsqrt_rn(192.0f);
        float denom = __fadd_rn(rmax, 1e-6f);
        float r = __fsqrt_rn((float)k2);
        float q = __fmul_rn(__fdiv_rn(r, denom), 16.0f);
        int s = (int)q;
        if (s > 15) s = 15;
        g_shell[m] = s;
        float inv = (k2 > 0) ? __fdiv_rn(1.0f, r) : 0.0f;
        float ux = fx * inv, uy = fy * inv, uz = fz * inv;
        float nzm = k2 > 0 ? 1.0f : 0.0f;
        float* Y = &g_YW[m * 9];
        Y[0] = 0.282095f;
        Y[1] = 0.488603f * uy;
        Y[2] = 0.488603f * uz;
        Y[3] = 0.488603f * ux;
        Y[4] = 1.092548f * ux * uy;
        Y[5] = 1.092548f * uy * uz;
        Y[6] = 0.315392f * (3.0f * uz * uz - nzm);
        Y[7] = 1.092548f * ux * uz;
        Y[8] = 0.546274f * (ux * ux - uy * uy);
        if (blockIdx.x == 0 && threadIdx.x < 64) {
            int t = threadIdx.x;
            float ang = (float)(2.0 * M_PI * (double)t / 64.0);
            g_TW[t] = make_float2(cosf(ang), sinf(ang));
        }
    } else {
        int t = threadIdx.x;                 // 128
        int jg = t >> 5, c = t & 31;
        #pragma unroll
        for (int g = 0; g < 4; g++) {
            int j = jg + g*4;
            float ar = 0.f, ai = 0.f;
            for (int o = 0; o < 32; o++) {
                float ax = w1r[j*32+o], ay = w1i[j*32+o];
                float bx = wfr[o*32+c], by = wfi[o*32+c];
                ar += ax*bx - ay*by;
                ai += ax*by + ay*bx;
            }
            g_WC[j*32+c] = make_float2(ar, ai);
            if (c == 0) {
                float br = b1r[j], bi = b1i[j];
                for (int o = 0; o < 32; o++) {
                    float ax = w1r[j*32+o], ay = w1i[j*32+o];
                    float bx = bfr[o], by = bfi[o];
                    br += ax*bx - ay*by;
                    bi += ax*by + ay*bx;
                }
                g_BC[j] = make_float2(br, bi);
            }
        }
    }
}

// ---------------- K0b ----------------
__global__ void k0b_sort() {
    int s = blockIdx.x;
    int t = threadIdx.x;                 // 256
    __shared__ int hist[16];
    __shared__ int chunkcnt[128];
    __shared__ int chunkpre[128];
    __shared__ float wSs;
    __shared__ int offs;
    if (t < 16) hist[t] = 0;
    __syncthreads();
    for (int i = t; i < M4096; i += 256) atomicAdd(&hist[g_shell[i]], 1);
    if (t < 128) {
        int c = 0;
        #pragma unroll 8
        for (int e = 0; e < 32; e++) c += (g_shell[t*32+e] == s) ? 1 : 0;
        chunkcnt[t] = c;
    }
    __syncthreads();
    if (t == 0) {
        int off = 0;
        for (int s2 = 0; s2 < s; s2++) off += hist[s2];
        offs = off;
        g_off[s] = off;
        if (s == 15) g_off[16] = off + hist[15];
        wSs = __fdiv_rn(1.0f, __fsqrt_rn(fmaxf((float)hist[s], 1.0f)));
        int acc = 0;
        for (int c = 0; c < 128; c++) { chunkpre[c] = acc; acc += chunkcnt[c]; }
    }
    __syncthreads();
    int w = t >> 5, lane = t & 31;
    float wS = wSs;
    int off0 = offs;
    for (int cc = w; cc < 128; cc += 8) {
        int m = cc*32 + lane;
        bool mine = (g_shell[m] == s);
        unsigned msk = __ballot_sync(0xffffffffu, mine);
        if (mine) {
            int p = off0 + chunkpre[cc] + __popc(msk & ((1u << lane) - 1u));
            g_sorted[p] = m;
            #pragma unroll
            for (int l = 0; l < 9; l++) {
                float v = g_YW[m*9+l] * wS;
                g_YWT[l*M4096 + m]  = v;
                g_YWsT[l*M4096 + p] = v;
            }
        }
    }
}

// ---------------- K12: forward z-DFT (double fold) + y-DFT (half fold) ----------------
__global__ void k12_fwd(const float* __restrict__ x) {
    __shared__ __align__(16) float xp[64*68];
    __shared__ float2 S1[1024];
    __shared__ ull twA[16*33];     // (c,-s), cols 0..32
    __shared__ ull twB[16*33];     // (s, c)
    int blk = blockIdx.x;            // bc*64 + x
    int t = threadIdx.x;             // 256
    const float* src = x + (size_t)blk * 4096;
    #pragma unroll
    for (int it = 0; it < 4; it++) {
        int i = t + it*256;
        float4 v = *(const float4*)&src[i*4];
        int y = i >> 4, z0 = (i & 15) * 4;
        *(float4*)&xp[y*68 + z0] = v;
    }
    #pragma unroll
    for (int it = 0; it < 3; it++) {
        int i = t + it*256;
        if (i < 528) {
            int k = i / 33, j = i - k*33;
            int fk = k < 8 ? k : k - 16;
            float2 w = g_TW[(j * fk) & 63];
            twA[k*33 + j] = pk(w.x, -w.y);
            twB[k*33 + j] = pk(w.y, w.x);
        }
    }
    __syncthreads();
    {
        int y = t >> 2, q = t & 3;
        const float* row = &xp[y*68];
        float x0 = row[0], x32v = row[32];
        float sgn = (q & 1) ? -1.f : 1.f;
        ull sgnP = splat(sgn);
        ull a0 = pk(x0 + sgn*x32v, 0.f);
        ull a1 = a0;
        ull a2 = pk(x0 + x32v, 0.f);
        #pragma unroll
        for (int z = 1; z <= 15; z++) {
            float xa = row[z],      xb = row[64 - z];
            float xc = row[32 - z], xd = row[32 + z];
            float p  = xa + xb, md = xa - xb;
            float r  = xc + xd, td = xc - xd;
            ull base = pk(p, md);
            ull alt  = pk(r, -td);
            ull uvE  = add2(base, alt);
            ull uvQ  = ffma2(alt, sgnP, base);
            a2 = ffma2(uvE, twA[8*33 + z], a2);
            a0 = ffma2(uvQ, twA[q*33 + z], a0);
            a1 = ffma2(uvQ, twA[(q+4)*33 + z], a1);
        }
        {
            float xa = row[16], xb = row[48];
            ull uv16 = pk(xa + xb, xa - xb);
            a0 = ffma2(uv16, twA[q*33 + 16], a0);
            a1 = ffma2(uv16, twA[(q+4)*33 + 16], a1);
            a2 = ffma2(uv16, twA[8*33 + 16], a2);
        }
        float2 v0 = upk(a0), v1 = upk(a1), v2 = upk(a2);
        S1[y*16 + q]      = v0;
        S1[y*16 + q + 4]  = v1;
        S1[y*16 + 12 - q] = make_float2(v1.x, -v1.y);
        if (q > 0) S1[y*16 + 16 - q] = make_float2(v0.x, -v0.y);
        else       S1[y*16 + 8]      = v2;
    }
    __syncthreads();
    {
        int ky = t >> 4, kz = t & 15;
        ull sgnP = splat((ky & 1) ? -1.f : 1.f);
        ull acc = 0;
        #pragma unroll 4
        for (int y2 = 0; y2 < 32; y2++) {
            ull aU = *(const ull*)&S1[y2*16 + kz];
            ull bU = *(const ull*)&S1[(y2+32)*16 + kz];
            ull comb = ffma2(bU, sgnP, aU);
            float2 cb = upk(comb);
            acc = ffma2(splat(cb.x), twA[ky*33 + y2], acc);
            acc = ffma2(splat(cb.y), twB[ky*33 + y2], acc);
        }
        g_S2[(size_t)blk * 256 + t] = upk(acc);
    }
}

// ---------------- K3: forward x-DFT with x<->x+32 fold, 8-way split ----------------
__global__ void k3_xdft() {
    __shared__ ull twA[16*33];
    __shared__ ull twB[16*33];
    int bc = blockIdx.x >> 3;
    int tq = blockIdx.x & 7;
    int tid = threadIdx.x;           // 256
    int kxg = tid >> 5, tl = tid & 31;
    int t = tq * 32 + tl;
    for (int i = tid; i < 512; i += 256) {
        int k = i >> 5, j = i & 31;
        int fk = k < 8 ? k : k - 16;
        float2 w = g_TW[(j * fk) & 63];
        twA[k*33 + j] = pk(w.x, -w.y);
        twB[k*33 + j] = pk(w.y, w.x);
    }
    __syncthreads();
    ull acc0 = 0, acc1 = 0;
    const float2* src = g_S2 + (size_t)bc * 16384;
    ull neg1 = splat(-1.f);
    int kx0 = kxg * 2;
    #pragma unroll 4
    for (int xx = 0; xx < 32; xx++) {
        ull aU = *(const ull*)&src[xx*256 + t];
        ull bU = *(const ull*)&src[(xx+32)*256 + t];
        ull p = add2(aU, bU);
        ull mm = ffma2(bU, neg1, aU);
        float2 pp = upk(p), mv = upk(mm);
        acc0 = ffma2(splat(pp.x), twA[kx0*33 + xx], acc0);
        acc0 = ffma2(splat(pp.y), twB[kx0*33 + xx], acc0);
        acc1 = ffma2(splat(mv.x), twA[(kx0+1)*33 + xx], acc1);
        acc1 = ffma2(splat(mv.y), twB[(kx0+1)*33 + xx], acc1);
    }
    float2* dst = g_XS + (size_t)bc * 4096;
    dst[kx0*256 + t]     = upk(acc0);
    dst[(kx0+1)*256 + t] = upk(acc1);
}

// ---------------- K4: basis projection (smem-staged, 4-way split) ----------------
__global__ void k4_proj() {
    __shared__ __align__(16) float2 sxs[4096];
    int bc = blockIdx.x >> 2;
    int p  = blockIdx.x & 3;
    int tid = threadIdx.x;           // 256
    const float4* srcv = (const float4*)&g_XS[(size_t)bc * 4096];
    #pragma unroll
    for (int it = 0; it < 8; it++) {
        int i = tid + it*256;
        *(float4*)&sxs[i*2] = srcv[i];
    }
    __syncthreads();
    if (tid < K144) {
        int k = tid;
        int s = k / 9, l = k - s * 9;
        const float* ywp = &g_YWsT[l*M4096];
        int beg = g_off[s], end = g_off[s+1], len = end - beg;
        int i0 = beg + (len * p) / 4;
        int i1 = beg + (len * (p + 1)) / 4;
        ull acc0 = 0, acc1 = 0;
        int i = i0;
        for (; i + 2 <= i1; i += 2) {
            int m0 = g_sorted[i], m1 = g_sorted[i+1];
            float w0 = ywp[i], w1 = ywp[i+1];
            float2 u0 = sxs[m0], u1 = sxs[m1];
            acc0 = ffma2(splat(w0), pk(u0.x, u0.y), acc0);
            acc1 = ffma2(splat(w1), pk(u1.x, u1.y), acc1);
        }
        if (i < i1) {
            int m0 = g_sorted[i];
            float w0 = ywp[i];
            float2 u0 = sxs[m0];
            acc0 = ffma2(splat(w0), pk(u0.x, u0.y), acc0);
        }
        float2 a = upk(acc0), bb = upk(acc1);
        g_C1P[((size_t)bc*4 + p)*K144 + k] = make_float2(a.x + bb.x, a.y + bb.y);
    }
}

// ---------------- K5: spectral conv fused with W1 (4 partials) ----------------
__global__ void k5_conv(const float* __restrict__ wr, const float* __restrict__ wi,
                        const float* __restrict__ w1r, const float* __restrict__ w1i) {
    __shared__ float2 cin[32];
    __shared__ float2 c2s[32];
    int blk = blockIdx.x;            // b*144 + sl
    int b = blk / K144, sl = blk - b * K144;
    int o = threadIdx.x;             // 32
    {
        size_t base = ((size_t)(b*32 + o))*4*K144 + sl;
        float2 a = g_C1P[base], bb = g_C1P[base + K144];
        float2 c = g_C1P[base + 2*K144], d = g_C1P[base + 3*K144];
        cin[o] = make_float2(a.x+bb.x+c.x+d.x, a.y+bb.y+c.y+d.y);
    }
    __syncwarp();
    const float* wrp = wr + (size_t)sl * 1024 + o;
    const float* wip = wi + (size_t)sl * 1024 + o;
    float ar = 0.f, ai = 0.f;
    #pragma unroll
    for (int i = 0; i < 32; i++) {
        float2 c = cin[i];
        float a = wrp[i*32], bb = wip[i*32];
        ar += c.x*a - c.y*bb;
        ai += c.x*bb + c.y*a;
    }
    const float invn = 1.0f / 262144.0f;
    c2s[o] = make_float2(ar*invn, ai*invn);
    __syncwarp();
    if (o < HID) {
        int j = o;
        float br = 0.f, bi = 0.f;
        #pragma unroll
        for (int q = 0; q < 32; q++) {
            float ax = w1r[j*32+q], ay = w1i[j*32+q];
            float2 c = c2s[q];
            br += ax*c.x - ay*c.y;
            bi += ax*c.y + ay*c.x;
        }
        g_C3[((size_t)(b*HID + j))*K144 + sl] = make_float2(br, bi);
    }
}

// ---------------- K67: inverse basis (coalesced) + inverse x/y-DFT (E/O fold) ----------------
__global__ void k67_inv() {
    __shared__ ull c3[K144];
    __shared__ ull twiA[16*33];
    __shared__ ull twiB[16*33];
    __shared__ float2 SA[256];
    __shared__ float2 SB[256];
    int bj = blockIdx.x >> 4;
    int xo = blockIdx.x & 15;
    int b = bj >> 4, j = bj & 15;
    int t = threadIdx.x;             // 256
    if (t < K144) {
        float2 v = g_C3[(size_t)bj*K144 + t];
        c3[t] = pk(v.x, v.y);
    }
    for (int i = t; i < 512; i += 256) {
        int k = i >> 5, col = i & 31;
        int fk = k < 8 ? k : k - 16;
        float2 w = g_TW[(col * fk) & 63];
        twiA[k*33 + col] = pk(w.x, w.y);
        twiB[k*33 + col] = pk(-w.y, w.x);
    }
    __syncthreads();
    ull xs2[16];
    #pragma unroll
    for (int kx = 0; kx < 16; kx++) {
        int m = (kx << 8) | t;
        int s = g_shell[m];
        ull acc = 0;
        #pragma unroll
        for (int l = 0; l < 9; l++)
            acc = ffma2(splat(g_YWT[l*M4096 + m]), c3[s*9 + l], acc);
        xs2[kx] = acc;
    }
    ull neg1 = splat(-1.f);
    int yp = t >> 3;
    int kzq = t & 7;
    #pragma unroll
    for (int xh = 0; xh < 2; xh++) {
        int xl = xo*2 + xh;
        {
            ull E = 0, O = 0;
            #pragma unroll
            for (int kx = 0; kx < 16; kx++) {
                float2 v = upk(xs2[kx]);
                ull wA = twiA[kx*33 + xl], wB = twiB[kx*33 + xl];
                if (kx & 1) {
                    O = ffma2(splat(v.x), wA, O);
                    O = ffma2(splat(v.y), wB, O);
                } else {
                    E = ffma2(splat(v.x), wA, E);
                    E = ffma2(splat(v.y), wB, E);
                }
            }
            SA[t] = upk(add2(E, O));
            SB[t] = upk(ffma2(O, neg1, E));
        }
        __syncthreads();
        #pragma unroll
        for (int xi = 0; xi < 2; xi++) {
            const float2* S = xi ? SB : SA;
            int xx = xl + 32*xi;
            float2 r0[2], r1[2];
            #pragma unroll
            for (int k2 = 0; k2 < 2; k2++) {
                int kz = kzq*2 + k2;
                ull E = 0, O = 0;
                #pragma unroll
                for (int ky = 0; ky < 16; ky++) {
                    float2 v = S[ky*16 + kz];
                    ull wA = twiA[ky*33 + yp], wB = twiB[ky*33 + yp];
                    if (ky & 1) {
                        O = ffma2(splat(v.x), wA, O);
                        O = ffma2(splat(v.y), wB, O);
                    } else {
                        E = ffma2(splat(v.x), wA, E);
                        E = ffma2(splat(v.y), wB, E);
                    }
                }
                r0[k2] = upk(add2(E, O));
                r1[k2] = upk(ffma2(O, neg1, E));
            }
            size_t base = ((size_t)b*64 + xx)*64;
            float4 w0 = make_float4(r0[0].x, r0[0].y, r0[1].x, r0[1].y);
            float4 w1 = make_float4(r1[0].x, r1[0].y, r1[1].x, r1[1].y);
            *(float4*)&g_T2[(base + yp)*256 + j*16 + kzq*2]      = w0;
            *(float4*)&g_T2[(base + yp + 32)*256 + j*16 + kzq*2] = w1;
        }
        __syncthreads();
    }
}

// ---------------- K8: fused epilogue with E/O z-fold via SMEM exchange ----------------
__device__ __forceinline__ float gelu_t(float v) {
    float u = 0.7978845608028654f * (v + 0.044715f * v * v * v);
    float e = __expf(2.0f * u);
    float th = 1.0f - 2.0f / (e + 1.0f);
    return 0.5f * v * (1.0f + th);
}

#define K8_SMEM 49536

__global__ void __launch_bounds__(128, 4)
k8_final(const float* __restrict__ x,
         const float* __restrict__ wgr,
         const float* __restrict__ w2r, const float* __restrict__ w2i,
         const float* __restrict__ b2r,
         float* __restrict__ out) {
    extern __shared__ char sm[];
    float* s_x   = (float*)sm;               // [2][32][64]   16384
    float* s_t2x = (float*)(sm + 16384);     // [2][16kz][16j] 2048
    float* s_t2y = (float*)(sm + 18432);     //                2048
    float* s_twc = (float*)(sm + 20480);     // [16kz][32z0]   2048
    float* s_tws = (float*)(sm + 22528);     //                2048
    float* s_wcR = (float*)(sm + 24576);     // [32c][16j]     2048
    float* s_wcI = (float*)(sm + 26624);     //                2048
    float* s_w2r = (float*)(sm + 28672);     // [16j][32o]     2048
    float* s_w2n = (float*)(sm + 30720);     //                2048
    float* s_bcR = (float*)(sm + 32768);     // 64
    float* s_bcI = (float*)(sm + 32832);     // 64
    float* s_b2  = (float*)(sm + 32896);     // 128
    float* s_wg  = (float*)(sm + 33024);     // 128
    ull*   s_ex  = (ull*)(sm + 33152);       // [16 slot][128 t] 16384

    int blk = blockIdx.x;
    int b  = blk >> 11;
    int xc = (blk >> 5) & 63;
    int y0 = (blk & 31) * 2;
    int t = threadIdx.x;             // 128

    #pragma unroll
    for (int it = 0; it < 8; it++) {
        int i = t + it*128;
        int line = i >> 9, c = (i >> 4) & 31, zq = i & 15;
        float4 v = *(const float4*)&x[(((size_t)(b*32+c))*64 + xc)*4096 + (size_t)(y0+line)*64 + zq*4];
        *(float4*)&s_x[(line*32+c)*64 + zq*4] = v;
    }
    #pragma unroll
    for (int it = 0; it < 4; it++) {
        int i = t + it*128;
        int line = i >> 8, q = i & 255;
        int j = q >> 4, kz = q & 15;
        float2 v = g_T2[((((size_t)b*64 + xc)*64) + (y0+line))*256 + q];
        s_t2x[(line*16 + kz)*16 + j] = v.x;
        s_t2y[(line*16 + kz)*16 + j] = v.y;
    }
    #pragma unroll
    for (int it = 0; it < 4; it++) {
        int i = t + it*128;
        int kz = i >> 5, z0 = i & 31;
        int fk = kz < 8 ? kz : kz - 16;
        float2 w = g_TW[(z0*fk) & 63];
        s_twc[i] = w.x;
        s_tws[i] = w.y;
    }
    #pragma unroll
    for (int it = 0; it < 4; it++) {
        int i = t + it*128;
        int c = i >> 4, j = i & 15;
        float2 wv = g_WC[j*32 + c];
        s_wcR[c*16 + j] = wv.x;
        s_wcI[c*16 + j] = wv.y;
        int jj = i >> 5, o = i & 31;
        s_w2r[jj*32 + o] = w2r[o*16 + jj];
        s_w2n[jj*32 + o] = -w2i[o*16 + jj];
    }
    if (t < 32) {
        s_b2[t] = b2r[t];
        s_wg[t] = wgr[t];
        if (t < 16) { float2 v = g_BC[t]; s_bcR[t] = v.x; s_bcI[t] = v.y; }
    }
    __syncthreads();

    int line = t >> 6;
    int zh   = t & 63;
    int isO  = zh >> 5;              // 0 = even-kz role, 1 = odd-kz role
    int z0   = zh & 31;
    int myz  = z0 + (isO << 5);      // this thread's output z
    const float* xl = &s_x[line*2048];

    // ---- partial kz-reduction (8 kz of my parity) ----
    ull pR[8] = {0,0,0,0,0,0,0,0}, pI[8] = {0,0,0,0,0,0,0,0};
    #pragma unroll
    for (int kk = 0; kk < 8; kk++) {
        int kz = isO + kk*2;
        float cw = s_twc[kz*32 + z0], sw = s_tws[kz*32 + z0];
        ull sc = splat(cw), ss = splat(sw), sn = splat(-sw);
        const ulonglong2* tx = (const ulonglong2*)&s_t2x[(line*16 + kz)*16];
        const ulonglong2* ty = (const ulonglong2*)&s_t2y[(line*16 + kz)*16];
        #pragma unroll
        for (int p = 0; p < 4; p++) {
            ulonglong2 a = tx[p], bv = ty[p];
            pR[2*p]   = ffma2(a.x,  sc, pR[2*p]);
            pR[2*p]   = ffma2(bv.x, sn, pR[2*p]);
            pI[2*p]   = ffma2(a.x,  ss, pI[2*p]);
            pI[2*p]   = ffma2(bv.x, sc, pI[2*p]);
            pR[2*p+1] = ffma2(a.y,  sc, pR[2*p+1]);
            pR[2*p+1] = ffma2(bv.y, sn, pR[2*p+1]);
            pI[2*p+1] = ffma2(a.y,  ss, pI[2*p+1]);
            pI[2*p+1] = ffma2(bv.y, sc, pI[2*p+1]);
        }
    }
    // ---- exchange partials: slot-major layout, partner = t ^ 32 ----
    #pragma unroll
    for (int jp = 0; jp < 8; jp++) {
        s_ex[jp*128 + t]       = pR[jp];
        s_ex[(8+jp)*128 + t]   = pI[jp];
    }
    __syncthreads();
    int pt = t ^ 32;
    ull sgnU = splat(isO ? -1.f : 1.f);
    ull accR[8], accI[8];
    #pragma unroll
    for (int jp = 0; jp < 8; jp++) {
        ull oR = s_ex[jp*128 + pt];
        ull oI = s_ex[(8+jp)*128 + pt];
        // E-role: bc + p + o ; O-role: bc + o - p
        accR[jp] = ffma2(pR[jp], sgnU, add2(oR, *(const ull*)&s_bcR[jp*2]));
        accI[jp] = ffma2(pI[jp], sgnU, add2(oI, *(const ull*)&s_bcI[jp*2]));
    }

    // ---- Wc * x for my voxel ----
    #pragma unroll 4
    for (int c = 0; c < 32; c++) {
        ull sx = splat(xl[c*64 + myz]);
        const ulonglong2* wr = (const ulonglong2*)&s_wcR[c*16];
        const ulonglong2* wi = (const ulonglong2*)&s_wcI[c*16];
        #pragma unroll
        for (int p = 0; p < 4; p++) {
            ulonglong2 a = wr[p], bv = wi[p];
            accR[2*p]   = ffma2(a.x,  sx, accR[2*p]);
            accR[2*p+1] = ffma2(a.y,  sx, accR[2*p+1]);
            accI[2*p]   = ffma2(bv.x, sx, accI[2*p]);
            accI[2*p+1] = ffma2(bv.y, sx, accI[2*p+1]);
        }
    }

    float hrf[16], hif[16];
    #pragma unroll
    for (int jp = 0; jp < 8; jp++) {
        float2 r  = upk(accR[jp]);
        float2 im = upk(accI[jp]);
        hrf[2*jp]   = gelu_t(r.x);
        hrf[2*jp+1] = gelu_t(r.y);
        hif[2*jp]   = gelu_t(im.x);
        hif[2*jp+1] = gelu_t(im.y);
    }

    // ---- pass 2: out = Re(W2 h) + b2 + x*wg ----
    int y = y0 + line;
    size_t obase = (((size_t)(b*32))*64 + xc)*4096 + (size_t)y*64 + myz;
    #pragma unroll
    for (int h = 0; h < 2; h++) {
        ull accO[8];
        #pragma unroll
        for (int op = 0; op < 8; op++) {
            int o = h*16 + op*2;
            ull b2p = *(const ull*)&s_b2[o];
            ull wgp = *(const ull*)&s_wg[o];
            ull xp  = pk(xl[o*64 + myz], xl[(o+1)*64 + myz]);
            accO[op] = ffma2(xp, wgp, b2p);
        }
        #pragma unroll
        for (int j = 0; j < 16; j++) {
            ull shr = splat(hrf[j]), shi = splat(hif[j]);
            const ulonglong2* wr = (const ulonglong2*)&s_w2r[j*32 + h*16];
            const ulonglong2* wn = (const ulonglong2*)&s_w2n[j*32 + h*16];
            #pragma unroll
            for (int p = 0; p < 4; p++) {
                ulonglong2 a = wr[p], bv = wn[p];
                accO[2*p]   = ffma2(a.x,  shr, accO[2*p]);
                accO[2*p]   = ffma2(bv.x, shi, accO[2*p]);
                accO[2*p+1] = ffma2(a.y,  shr, accO[2*p+1]);
                accO[2*p+1] = ffma2(bv.y, shi, accO[2*p+1]);
            }
        }
        #pragma unroll
        for (int op = 0; op < 8; op++) {
            int o = h*16 + op*2;
            float2 v = upk(accO[op]);
            out[obase + (size_t)o     * 262144] = v.x;
            out[obase + (size_t)(o+1) * 262144] = v.y;
        }
    }
}

// ---------------- launch ----------------
extern "C" void kernel_launch(void* const* d_in, const int* in_sizes, int n_in,
                              void* d_out, int out_size) {
    const float* x    = (const float*)d_in[0];
    const float* wfr  = (const float*)d_in[1];
    const float* wfi  = (const float*)d_in[2];
    const float* bfr  = (const float*)d_in[3];
    const float* bfi  = (const float*)d_in[4];
    const float* wgr  = (const float*)d_in[5];
    const float* wsr  = (const float*)d_in[7];
    const float* wsi  = (const float*)d_in[8];
    const float* w1r  = (const float*)d_in[9];
    const float* w1i  = (const float*)d_in[10];
    const float* b1r  = (const float*)d_in[11];
    const float* b1i  = (const float*)d_in[12];
    const float* w2r  = (const float*)d_in[13];
    const float* w2i  = (const float*)d_in[14];
    const float* b2r  = (const float*)d_in[15];
    float* out = (float*)d_out;

    cudaFuncSetAttribute(k8_final, cudaFuncAttributeMaxDynamicSharedMemorySize, K8_SMEM);

    k0a_init<<<33, 128>>>(wfr, wfi, bfr, bfi, w1r, w1i, b1r, b1i);
    k0b_sort<<<16, 256>>>();
    k12_fwd<<<BB*CC*64, 256>>>(x);
    k3_xdft<<<BB*CC*8, 256>>>();
    k4_proj<<<BB*CC*4, 256>>>();
    k5_conv<<<BB*K144, 32>>>(wsr, wsi, w1r, w1i);
    k67_inv<<<BB*HID*16, 256>>>();
    k8_final<<<BB*64*32, 128, K8_SMEM>>>(x, wgr, w2r, w2i, b2r, out);
}

// round 15
// speedup vs baseline: 1.0240x; 1.0240x over previous
#include <cuda_runtime.h>
#include <math.h>

// ---------------- problem constants ----------------
#define BB 2
#define CC 32
#define HID 16
#define K144 144
#define M4096 4096

typedef unsigned long long ull;

// ---------------- packed f32x2 helpers ----------------
__device__ __forceinline__ ull pk(float lo, float hi) {
    ull r; asm("mov.b64 %0, {%1,%2};" : "=l"(r) : "f"(lo), "f"(hi)); return r;
}
__device__ __forceinline__ ull splat(float v) { return pk(v, v); }
__device__ __forceinline__ float2 upk(ull v) {
    float2 r; asm("mov.b64 {%0,%1}, %2;" : "=f"(r.x), "=f"(r.y) : "l"(v)); return r;
}
__device__ __forceinline__ ull ffma2(ull a, ull b, ull c) {
    ull d; asm("fma.rn.f32x2 %0, %1, %2, %3;" : "=l"(d) : "l"(a), "l"(b), "l"(c)); return d;
}
__device__ __forceinline__ ull add2(ull a, ull b) {
    ull d; asm("add.rn.f32x2 %0, %1, %2;" : "=l"(d) : "l"(a), "l"(b)); return d;
}

// ---------------- device scratch ----------------
__device__ __align__(16) float2 g_S2[BB*CC*64*256];
__device__ __align__(16) float2 g_XS[BB*CC*M4096];
__device__ __align__(16) float2 g_C1P[BB*CC*8*K144];
__device__ __align__(16) float2 g_C3[BB*HID*K144];
__device__ __align__(16) float2 g_T2[BB*64*64*256];
__device__ int    g_shell[M4096];
__device__ __align__(16) float g_YW[M4096*9];      // unscaled, [m][l]
__device__ __align__(16) float g_YWT[9*M4096];     // scaled, [l][m]
__device__ __align__(16) float g_YWsT[9*M4096];    // scaled, [l][sorted p]
__device__ int    g_sorted[M4096];
__device__ int    g_off[17];
__device__ float2 g_TW[64];
__device__ float2 g_WC[HID*CC];
__device__ float2 g_BC[HID];

// ---------------- K0a: mode tables (blocks 0..31) + W1-fold (block 32) ----------------
__global__ void k0a_init(const float* __restrict__ wfr, const float* __restrict__ wfi,
                         const float* __restrict__ bfr, const float* __restrict__ bfi,
                         const float* __restrict__ w1r, const float* __restrict__ w1i,
                         const float* __restrict__ b1r, const float* __restrict__ b1i) {
    if (blockIdx.x < 32) {
        int m = blockIdx.x * 128 + threadIdx.x;
        int ix = m >> 8, iy = (m >> 4) & 15, iz = m & 15;
        int fx = ix < 8 ? ix : ix - 16;
        int fy = iy < 8 ? iy : iy - 16;
        int fz = iz < 8 ? iz : iz - 16;
        int k2 = fx*fx + fy*fy + fz*fz;
        float rmax  = __fsqrt_rn(192.0f);
        float denom = __fadd_rn(rmax, 1e-6f);
        float r = __fsqrt_rn((float)k2);
        float q = __fmul_rn(__fdiv_rn(r, denom), 16.0f);
        int s = (int)q;
        if (s > 15) s = 15;
        g_shell[m] = s;
        float inv = (k2 > 0) ? __fdiv_rn(1.0f, r) : 0.0f;
        float ux = fx * inv, uy = fy * inv, uz = fz * inv;
        float nzm = k2 > 0 ? 1.0f : 0.0f;
        float* Y = &g_YW[m * 9];
        Y[0] = 0.282095f;
        Y[1] = 0.488603f * uy;
        Y[2] = 0.488603f * uz;
        Y[3] = 0.488603f * ux;
        Y[4] = 1.092548f * ux * uy;
        Y[5] = 1.092548f * uy * uz;
        Y[6] = 0.315392f * (3.0f * uz * uz - nzm);
        Y[7] = 1.092548f * ux * uz;
        Y[8] = 0.546274f * (ux * ux - uy * uy);
        if (blockIdx.x == 0 && threadIdx.x < 64) {
            int t = threadIdx.x;
            float ang = (float)(2.0 * M_PI * (double)t / 64.0);
            g_TW[t] = make_float2(cosf(ang), sinf(ang));
        }
    } else {
        int t = threadIdx.x;                 // 128
        int jg = t >> 5, c = t & 31;
        #pragma unroll
        for (int g = 0; g < 4; g++) {
            int j = jg + g*4;
            float ar = 0.f, ai = 0.f;
            for (int o = 0; o < 32; o++) {
                float ax = w1r[j*32+o], ay = w1i[j*32+o];
                float bx = wfr[o*32+c], by = wfi[o*32+c];
                ar += ax*bx - ay*by;
                ai += ax*by + ay*bx;
            }
            g_WC[j*32+c] = make_float2(ar, ai);
            if (c == 0) {
                float br = b1r[j], bi = b1i[j];
                for (int o = 0; o < 32; o++) {
                    float ax = w1r[j*32+o], ay = w1i[j*32+o];
                    float bx = bfr[o], by = bfi[o];
                    br += ax*bx - ay*by;
                    bi += ax*by + ay*bx;
                }
                g_BC[j] = make_float2(br, bi);
            }
        }
    }
}

// ---------------- K0b ----------------
__global__ void k0b_sort() {
    int s = blockIdx.x;
    int t = threadIdx.x;                 // 256
    __shared__ int hist[16];
    __shared__ int chunkcnt[128];
    __shared__ int chunkpre[128];
    __shared__ float wSs;
    __shared__ int offs;
    if (t < 16) hist[t] = 0;
    __syncthreads();
    for (int i = t; i < M4096; i += 256) atomicAdd(&hist[g_shell[i]], 1);
    if (t < 128) {
        int c = 0;
        #pragma unroll 8
        for (int e = 0; e < 32; e++) c += (g_shell[t*32+e] == s) ? 1 : 0;
        chunkcnt[t] = c;
    }
    __syncthreads();
    if (t == 0) {
        int off = 0;
        for (int s2 = 0; s2 < s; s2++) off += hist[s2];
        offs = off;
        g_off[s] = off;
        if (s == 15) g_off[16] = off + hist[15];
        wSs = __fdiv_rn(1.0f, __fsqrt_rn(fmaxf((float)hist[s], 1.0f)));
        int acc = 0;
        for (int c = 0; c < 128; c++) { chunkpre[c] = acc; acc += chunkcnt[c]; }
    }
    __syncthreads();
    int w = t >> 5, lane = t & 31;
    float wS = wSs;
    int off0 = offs;
    for (int cc = w; cc < 128; cc += 8) {
        int m = cc*32 + lane;
        bool mine = (g_shell[m] == s);
        unsigned msk = __ballot_sync(0xffffffffu, mine);
        if (mine) {
            int p = off0 + chunkpre[cc] + __popc(msk & ((1u << lane) - 1u));
            g_sorted[p] = m;
            #pragma unroll
            for (int l = 0; l < 9; l++) {
                float v = g_YW[m*9+l] * wS;
                g_YWT[l*M4096 + m]  = v;
                g_YWsT[l*M4096 + p] = v;
            }
        }
    }
}

// ---------------- K12: forward z-DFT (double fold) + y-DFT (half fold) ----------------
__global__ void k12_fwd(const float* __restrict__ x) {
    __shared__ __align__(16) float xp[64*68];
    __shared__ float2 S1[1024];
    __shared__ ull twA[16*33];
    __shared__ ull twB[16*33];
    int blk = blockIdx.x;            // bc*64 + x
    int t = threadIdx.x;             // 256
    const float* src = x + (size_t)blk * 4096;
    #pragma unroll
    for (int it = 0; it < 4; it++) {
        int i = t + it*256;
        float4 v = *(const float4*)&src[i*4];
        int y = i >> 4, z0 = (i & 15) * 4;
        *(float4*)&xp[y*68 + z0] = v;
    }
    #pragma unroll
    for (int it = 0; it < 3; it++) {
        int i = t + it*256;
        if (i < 528) {
            int k = i / 33, j = i - k*33;
            int fk = k < 8 ? k : k - 16;
            float2 w = g_TW[(j * fk) & 63];
            twA[k*33 + j] = pk(w.x, -w.y);
            twB[k*33 + j] = pk(w.y, w.x);
        }
    }
    __syncthreads();
    {
        int y = t >> 2, q = t & 3;
        const float* row = &xp[y*68];
        float x0 = row[0], x32v = row[32];
        float sgn = (q & 1) ? -1.f : 1.f;
        ull sgnP = splat(sgn);
        ull a0 = pk(x0 + sgn*x32v, 0.f);
        ull a1 = a0;
        ull a2 = pk(x0 + x32v, 0.f);
        #pragma unroll
        for (int z = 1; z <= 15; z++) {
            float xa = row[z],      xb = row[64 - z];
            float xc = row[32 - z], xd = row[32 + z];
            float p  = xa + xb, md = xa - xb;
            float r  = xc + xd, td = xc - xd;
            ull base = pk(p, md);
            ull alt  = pk(r, -td);
            ull uvE  = add2(base, alt);
            ull uvQ  = ffma2(alt, sgnP, base);
            a2 = ffma2(uvE, twA[8*33 + z], a2);
            a0 = ffma2(uvQ, twA[q*33 + z], a0);
            a1 = ffma2(uvQ, twA[(q+4)*33 + z], a1);
        }
        {
            float xa = row[16], xb = row[48];
            ull uv16 = pk(xa + xb, xa - xb);
            a0 = ffma2(uv16, twA[q*33 + 16], a0);
            a1 = ffma2(uv16, twA[(q+4)*33 + 16], a1);
            a2 = ffma2(uv16, twA[8*33 + 16], a2);
        }
        float2 v0 = upk(a0), v1 = upk(a1), v2 = upk(a2);
        S1[y*16 + q]      = v0;
        S1[y*16 + q + 4]  = v1;
        S1[y*16 + 12 - q] = make_float2(v1.x, -v1.y);
        if (q > 0) S1[y*16 + 16 - q] = make_float2(v0.x, -v0.y);
        else       S1[y*16 + 8]      = v2;
    }
    __syncthreads();
    {
        int ky = t >> 4, kz = t & 15;
        ull sgnP = splat((ky & 1) ? -1.f : 1.f);
        ull acc = 0;
        #pragma unroll 4
        for (int y2 = 0; y2 < 32; y2++) {
            ull aU = *(const ull*)&S1[y2*16 + kz];
            ull bU = *(const ull*)&S1[(y2+32)*16 + kz];
            ull comb = ffma2(bU, sgnP, aU);
            float2 cb = upk(comb);
            acc = ffma2(splat(cb.x), twA[ky*33 + y2], acc);
            acc = ffma2(splat(cb.y), twB[ky*33 + y2], acc);
        }
        g_S2[(size_t)blk * 256 + t] = upk(acc);
    }
}

// ---------------- K3: forward x-DFT with x<->x+32 fold, 8-way split ----------------
__global__ void k3_xdft() {
    __shared__ ull twA[16*33];
    __shared__ ull twB[16*33];
    int bc = blockIdx.x >> 3;
    int tq = blockIdx.x & 7;
    int tid = threadIdx.x;           // 256
    int kxg = tid >> 5, tl = tid & 31;
    int t = tq * 32 + tl;
    for (int i = tid; i < 512; i += 256) {
        int k = i >> 5, j = i & 31;
        int fk = k < 8 ? k : k - 16;
        float2 w = g_TW[(j * fk) & 63];
        twA[k*33 + j] = pk(w.x, -w.y);
        twB[k*33 + j] = pk(w.y, w.x);
    }
    __syncthreads();
    ull acc0 = 0, acc1 = 0;
    const float2* src = g_S2 + (size_t)bc * 16384;
    ull neg1 = splat(-1.f);
    int kx0 = kxg * 2;
    #pragma unroll 4
    for (int xx = 0; xx < 32; xx++) {
        ull aU = *(const ull*)&src[xx*256 + t];
        ull bU = *(const ull*)&src[(xx+32)*256 + t];
        ull p = add2(aU, bU);
        ull mm = ffma2(bU, neg1, aU);
        float2 pp = upk(p), mv = upk(mm);
        acc0 = ffma2(splat(pp.x), twA[kx0*33 + xx], acc0);
        acc0 = ffma2(splat(pp.y), twB[kx0*33 + xx], acc0);
        acc1 = ffma2(splat(mv.x), twA[(kx0+1)*33 + xx], acc1);
        acc1 = ffma2(splat(mv.y), twB[(kx0+1)*33 + xx], acc1);
    }
    float2* dst = g_XS + (size_t)bc * 4096;
    dst[kx0*256 + t]     = upk(acc0);
    dst[(kx0+1)*256 + t] = upk(acc1);
}

// ---------------- K4: basis projection (smem-staged, 4-way split) ----------------
__global__ void k4_proj() {
    __shared__ __align__(16) float2 sxs[4096];
    int bc = blockIdx.x >> 2;
    int p  = blockIdx.x & 3;
    int tid = threadIdx.x;           // 256
    const float4* srcv = (const float4*)&g_XS[(size_t)bc * 4096];
    #pragma unroll
    for (int it = 0; it < 8; it++) {
        int i = tid + it*256;
        *(float4*)&sxs[i*2] = srcv[i];
    }
    __syncthreads();
    if (tid < K144) {
        int k = tid;
        int s = k / 9, l = k - s * 9;
        const float* ywp = &g_YWsT[l*M4096];
        int beg = g_off[s], end = g_off[s+1], len = end - beg;
        int i0 = beg + (len * p) / 4;
        int i1 = beg + (len * (p + 1)) / 4;
        ull acc0 = 0, acc1 = 0;
        int i = i0;
        for (; i + 2 <= i1; i += 2) {
            int m0 = g_sorted[i], m1 = g_sorted[i+1];
            float w0 = ywp[i], w1 = ywp[i+1];
            float2 u0 = sxs[m0], u1 = sxs[m1];
            acc0 = ffma2(splat(w0), pk(u0.x, u0.y), acc0);
            acc1 = ffma2(splat(w1), pk(u1.x, u1.y), acc1);
        }
        if (i < i1) {
            int m0 = g_sorted[i];
            float w0 = ywp[i];
            float2 u0 = sxs[m0];
            acc0 = ffma2(splat(w0), pk(u0.x, u0.y), acc0);
        }
        float2 a = upk(acc0), bb = upk(acc1);
        g_C1P[((size_t)bc*4 + p)*K144 + k] = make_float2(a.x + bb.x, a.y + bb.y);
    }
}

// ---------------- K5: spectral conv fused with W1 (4 partials) ----------------
__global__ void k5_conv(const float* __restrict__ wr, const float* __restrict__ wi,
                        const float* __restrict__ w1r, const float* __restrict__ w1i) {
    __shared__ float2 cin[32];
    __shared__ float2 c2s[32];
    int blk = blockIdx.x;            // b*144 + sl
    int b = blk / K144, sl = blk - b * K144;
    int o = threadIdx.x;             // 32
    {
        size_t base = ((size_t)(b*32 + o))*4*K144 + sl;
        float2 a = g_C1P[base], bb = g_C1P[base + K144];
        float2 c = g_C1P[base + 2*K144], d = g_C1P[base + 3*K144];
        cin[o] = make_float2(a.x+bb.x+c.x+d.x, a.y+bb.y+c.y+d.y);
    }
    __syncwarp();
    const float* wrp = wr + (size_t)sl * 1024 + o;
    const float* wip = wi + (size_t)sl * 1024 + o;
    float ar = 0.f, ai = 0.f;
    #pragma unroll
    for (int i = 0; i < 32; i++) {
        float2 c = cin[i];
        float a = wrp[i*32], bb = wip[i*32];
        ar += c.x*a - c.y*bb;
        ai += c.x*bb + c.y*a;
    }
    const float invn = 1.0f / 262144.0f;
    c2s[o] = make_float2(ar*invn, ai*invn);
    __syncwarp();
    if (o < HID) {
        int j = o;
        float br = 0.f, bi = 0.f;
        #pragma unroll
        for (int q = 0; q < 32; q++) {
            float ax = w1r[j*32+q], ay = w1i[j*32+q];
            float2 c = c2s[q];
            br += ax*c.x - ay*c.y;
            bi += ax*c.y + ay*c.x;
        }
        g_C3[((size_t)(b*HID + j))*K144 + sl] = make_float2(br, bi);
    }
}

// ---------------- K67: inverse basis (coalesced) + inverse x/y-DFT (E/O fold) ----------------
__global__ void k67_inv() {
    __shared__ ull c3[K144];
    __shared__ ull twiA[16*33];
    __shared__ ull twiB[16*33];
    __shared__ float2 SA[256];
    __shared__ float2 SB[256];
    int bj = blockIdx.x >> 4;
    int xo = blockIdx.x & 15;
    int b = bj >> 4, j = bj & 15;
    int t = threadIdx.x;             // 256
    if (t < K144) {
        float2 v = g_C3[(size_t)bj*K144 + t];
        c3[t] = pk(v.x, v.y);
    }
    for (int i = t; i < 512; i += 256) {
        int k = i >> 5, col = i & 31;
        int fk = k < 8 ? k : k - 16;
        float2 w = g_TW[(col * fk) & 63];
        twiA[k*33 + col] = pk(w.x, w.y);
        twiB[k*33 + col] = pk(-w.y, w.x);
    }
    __syncthreads();
    ull xs2[16];
    #pragma unroll
    for (int kx = 0; kx < 16; kx++) {
        int m = (kx << 8) | t;
        int s = g_shell[m];
        ull acc = 0;
        #pragma unroll
        for (int l = 0; l < 9; l++)
            acc = ffma2(splat(g_YWT[l*M4096 + m]), c3[s*9 + l], acc);
        xs2[kx] = acc;
    }
    ull neg1 = splat(-1.f);
    int yp = t >> 3;
    int kzq = t & 7;
    #pragma unroll
    for (int xh = 0; xh < 2; xh++) {
        int xl = xo*2 + xh;
        {
            ull E = 0, O = 0;
            #pragma unroll
            for (int kx = 0; kx < 16; kx++) {
                float2 v = upk(xs2[kx]);
                ull wA = twiA[kx*33 + xl], wB = twiB[kx*33 + xl];
                if (kx & 1) {
                    O = ffma2(splat(v.x), wA, O);
                    O = ffma2(splat(v.y), wB, O);
                } else {
                    E = ffma2(splat(v.x), wA, E);
                    E = ffma2(splat(v.y), wB, E);
                }
            }
            SA[t] = upk(add2(E, O));
            SB[t] = upk(ffma2(O, neg1, E));
        }
        __syncthreads();
        #pragma unroll
        for (int xi = 0; xi < 2; xi++) {
            const float2* S = xi ? SB : SA;
            int xx = xl + 32*xi;
            float2 r0[2], r1[2];
            #pragma unroll
            for (int k2 = 0; k2 < 2; k2++) {
                int kz = kzq*2 + k2;
                ull E = 0, O = 0;
                #pragma unroll
                for (int ky = 0; ky < 16; ky++) {
                    float2 v = S[ky*16 + kz];
                    ull wA = twiA[ky*33 + yp], wB = twiB[ky*33 + yp];
                    if (ky & 1) {
                        O = ffma2(splat(v.x), wA, O);
                        O = ffma2(splat(v.y), wB, O);
                    } else {
                        E = ffma2(splat(v.x), wA, E);
                        E = ffma2(splat(v.y), wB, E);
                    }
                }
                r0[k2] = upk(add2(E, O));
                r1[k2] = upk(ffma2(O, neg1, E));
            }
            size_t base = ((size_t)b*64 + xx)*64;
            float4 w0 = make_float4(r0[0].x, r0[0].y, r0[1].x, r0[1].y);
            float4 w1 = make_float4(r1[0].x, r1[0].y, r1[1].x, r1[1].y);
            *(float4*)&g_T2[(base + yp)*256 + j*16 + kzq*2]      = w0;
            *(float4*)&g_T2[(base + yp + 32)*256 + j*16 + kzq*2] = w1;
        }
        __syncthreads();
    }
}

// ---------------- K8: fused epilogue, E/O z-fold via intra-warp SHFL ----------------
__device__ __forceinline__ float gelu_t(float v) {
    float u = 0.7978845608028654f * (v + 0.044715f * v * v * v);
    float e = __expf(2.0f * u);
    float th = 1.0f - 2.0f / (e + 1.0f);
    return 0.5f * v * (1.0f + th);
}

#define K8_SMEM 33280

__global__ void __launch_bounds__(128, 5)
k8_final(const float* __restrict__ x,
         const float* __restrict__ wgr,
         const float* __restrict__ w2r, const float* __restrict__ w2i,
         const float* __restrict__ b2r,
         float* __restrict__ out) {
    extern __shared__ char sm[];
    float* s_x   = (float*)sm;               // [2][32][64]   16384
    float* s_t2x = (float*)(sm + 16384);     // [2][16kz][16j] 2048
    float* s_t2y = (float*)(sm + 18432);     //                2048
    float* s_twc = (float*)(sm + 20480);     // [16kz][32z0]   2048
    float* s_tws = (float*)(sm + 22528);     //                2048
    float* s_wcR = (float*)(sm + 24576);     // [32c][16j]     2048
    float* s_wcI = (float*)(sm + 26624);     //                2048
    float* s_w2r = (float*)(sm + 28672);     // [16j][32o]     2048
    float* s_w2n = (float*)(sm + 30720);     //                2048
    float* s_bcR = (float*)(sm + 32768);     // 64
    float* s_bcI = (float*)(sm + 32832);     // 64
    float* s_b2  = (float*)(sm + 32896);     // 128
    float* s_wg  = (float*)(sm + 33024);     // 128

    int blk = blockIdx.x;
    int b  = blk >> 11;
    int xc = (blk >> 5) & 63;
    int y0 = (blk & 31) * 2;
    int t = threadIdx.x;             // 128

    #pragma unroll
    for (int it = 0; it < 8; it++) {
        int i = t + it*128;
        int line = i >> 9, c = (i >> 4) & 31, zq = i & 15;
        float4 v = *(const float4*)&x[(((size_t)(b*32+c))*64 + xc)*4096 + (size_t)(y0+line)*64 + zq*4];
        *(float4*)&s_x[(line*32+c)*64 + zq*4] = v;
    }
    #pragma unroll
    for (int it = 0; it < 4; it++) {
        int i = t + it*128;
        int line = i >> 8, q = i & 255;
        int j = q >> 4, kz = q & 15;
        float2 v = g_T2[((((size_t)b*64 + xc)*64) + (y0+line))*256 + q];
        s_t2x[(line*16 + kz)*16 + j] = v.x;
        s_t2y[(line*16 + kz)*16 + j] = v.y;
    }
    #pragma unroll
    for (int it = 0; it < 4; it++) {
        int i = t + it*128;
        int kz = i >> 5, z0i = i & 31;
        int fk = kz < 8 ? kz : kz - 16;
        float2 w = g_TW[(z0i*fk) & 63];
        s_twc[i] = w.x;
        s_tws[i] = w.y;
    }
    #pragma unroll
    for (int it = 0; it < 4; it++) {
        int i = t + it*128;
        int c = i >> 4, j = i & 15;
        float2 wv = g_WC[j*32 + c];
        s_wcR[c*16 + j] = wv.x;
        s_wcI[c*16 + j] = wv.y;
        int jj = i >> 5, o = i & 31;
        s_w2r[jj*32 + o] = w2r[o*16 + jj];
        s_w2n[jj*32 + o] = -w2i[o*16 + jj];
    }
    if (t < 32) {
        s_b2[t] = b2r[t];
        s_wg[t] = wgr[t];
        if (t < 16) { float2 v = g_BC[t]; s_bcR[t] = v.x; s_bcI[t] = v.y; }
    }
    __syncthreads();

    // thread map: partner (other kz-parity, same z0) = t^16, SAME warp
    int line = t >> 6;
    int zh   = t & 63;
    int isO  = (zh >> 4) & 1;
    int z0   = (zh & 15) | ((zh >> 5) << 4);
    int myz  = z0 + (isO << 5);
    const float* xl = &s_x[line*2048];

    // ---- partial kz-reduction: 8 kz of my parity ----
    ull accR[8] = {0,0,0,0,0,0,0,0}, accI[8] = {0,0,0,0,0,0,0,0};
    #pragma unroll
    for (int kk = 0; kk < 8; kk++) {
        int kz = kk*2 + isO;
        float cw = s_twc[kz*32 + z0], sw = s_tws[kz*32 + z0];
        ull sc = splat(cw), ss = splat(sw), sn = splat(-sw);
        const ulonglong2* tx = (const ulonglong2*)&s_t2x[(line*16 + kz)*16];
        const ulonglong2* ty = (const ulonglong2*)&s_t2y[(line*16 + kz)*16];
        #pragma unroll
        for (int p = 0; p < 4; p++) {
            ulonglong2 a = tx[p], bv = ty[p];
            accR[2*p]   = ffma2(a.x,  sc, accR[2*p]);
            accR[2*p]   = ffma2(bv.x, sn, accR[2*p]);
            accI[2*p]   = ffma2(a.x,  ss, accI[2*p]);
            accI[2*p]   = ffma2(bv.x, sc, accI[2*p]);
            accR[2*p+1] = ffma2(a.y,  sc, accR[2*p+1]);
            accR[2*p+1] = ffma2(bv.y, sn, accR[2*p+1]);
            accI[2*p+1] = ffma2(a.y,  ss, accI[2*p+1]);
            accI[2*p+1] = ffma2(bv.y, sc, accI[2*p+1]);
        }
    }
    // ---- intra-warp exchange + combine: g = bc + other + sgn*own ----
    {
        ull sgnU = splat(isO ? -1.f : 1.f);
        #pragma unroll
        for (int jp = 0; jp < 8; jp++) {
            ull oR = __shfl_xor_sync(0xffffffffu, accR[jp], 16);
            ull oI = __shfl_xor_sync(0xffffffffu, accI[jp], 16);
            accR[jp] = ffma2(accR[jp], sgnU, add2(oR, *(const ull*)&s_bcR[jp*2]));
            accI[jp] = ffma2(accI[jp], sgnU, add2(oI, *(const ull*)&s_bcI[jp*2]));
        }
    }

    // ---- Wc * x for my voxel ----
    #pragma unroll 4
    for (int c = 0; c < 32; c++) {
        ull sx = splat(xl[c*64 + myz]);
        const ulonglong2* wr = (const ulonglong2*)&s_wcR[c*16];
        const ulonglong2* wi = (const ulonglong2*)&s_wcI[c*16];
        #pragma unroll
        for (int p = 0; p < 4; p++) {
            ulonglong2 a = wr[p], bv = wi[p];
            accR[2*p]   = ffma2(a.x,  sx, accR[2*p]);
            accR[2*p+1] = ffma2(a.y,  sx, accR[2*p+1]);
            accI[2*p]   = ffma2(bv.x, sx, accI[2*p]);
            accI[2*p+1] = ffma2(bv.y, sx, accI[2*p+1]);
        }
    }

    float hrf[16], hif[16];
    #pragma unroll
    for (int jp = 0; jp < 8; jp++) {
        float2 r  = upk(accR[jp]);
        float2 im = upk(accI[jp]);
        hrf[2*jp]   = gelu_t(r.x);
        hrf[2*jp+1] = gelu_t(r.y);
        hif[2*jp]   = gelu_t(im.x);
        hif[2*jp+1] = gelu_t(im.y);
    }

    // ---- pass 2: out = Re(W2 h) + b2 + x*wg ----
    int y = y0 + line;
    size_t obase = (((size_t)(b*32))*64 + xc)*4096 + (size_t)y*64 + myz;
    #pragma unroll
    for (int h = 0; h < 2; h++) {
        ull accO[8];
        #pragma unroll
        for (int op = 0; op < 8; op++) {
            int o = h*16 + op*2;
            ull b2p = *(const ull*)&s_b2[o];
            ull wgp = *(const ull*)&s_wg[o];
            ull xp  = pk(xl[o*64 + myz], xl[(o+1)*64 + myz]);
            accO[op] = ffma2(xp, wgp, b2p);
        }
        #pragma unroll
        for (int j = 0; j < 16; j++) {
            ull shr = splat(hrf[j]), shi = splat(hif[j]);
            const ulonglong2* wr = (const ulonglong2*)&s_w2r[j*32 + h*16];
            const ulonglong2* wn = (const ulonglong2*)&s_w2n[j*32 + h*16];
            #pragma unroll
            for (int p = 0; p < 4; p++) {
                ulonglong2 a = wr[p], bv = wn[p];
                accO[2*p]   = ffma2(a.x,  shr, accO[2*p]);
                accO[2*p]   = ffma2(bv.x, shi, accO[2*p]);
                accO[2*p+1] = ffma2(a.y,  shr, accO[2*p+1]);
                accO[2*p+1] = ffma2(bv.y, shi, accO[2*p+1]);
            }
        }
        #pragma unroll
        for (int op = 0; op < 8; op++) {
            int o = h*16 + op*2;
            float2 v = upk(accO[op]);
            out[obase + (size_t)o     * 262144] = v.x;
            out[obase + (size_t)(o+1) * 262144] = v.y;
        }
    }
}

// ---------------- launch ----------------
extern "C" void kernel_launch(void* const* d_in, const int* in_sizes, int n_in,
                              void* d_out, int out_size) {
    const float* x    = (const float*)d_in[0];
    const float* wfr  = (const float*)d_in[1];
    const float* wfi  = (const float*)d_in[2];
    const float* bfr  = (const float*)d_in[3];
    const float* bfi  = (const float*)d_in[4];
    const float* wgr  = (const float*)d_in[5];
    const float* wsr  = (const float*)d_in[7];
    const float* wsi  = (const float*)d_in[8];
    const float* w1r  = (const float*)d_in[9];
    const float* w1i  = (const float*)d_in[10];
    const float* b1r  = (const float*)d_in[11];
    const float* b1i  = (const float*)d_in[12];
    const float* w2r  = (const float*)d_in[13];
    const float* w2i  = (const float*)d_in[14];
    const float* b2r  = (const float*)d_in[15];
    float* out = (float*)d_out;

    cudaFuncSetAttribute(k8_final, cudaFuncAttributeMaxDynamicSharedMemorySize, K8_SMEM);

    k0a_init<<<33, 128>>>(wfr, wfi, bfr, bfi, w1r, w1i, b1r, b1i);
    k0b_sort<<<16, 256>>>();
    k12_fwd<<<BB*CC*64, 256>>>(x);
    k3_xdft<<<BB*CC*8, 256>>>();
    k4_proj<<<BB*CC*4, 256>>>();
    k5_conv<<<BB*K144, 32>>>(wsr, wsi, w1r, w1i);
    k67_inv<<<BB*HID*16, 256>>>();
    k8_final<<<BB*64*32, 128, K8_SMEM>>>(x, wgr, w2r, w2i, b2r, out);
}

// round 16
// speedup vs baseline: 1.0408x; 1.0164x over previous
#include <cuda_runtime.h>
#include <math.h>

// ---------------- problem constants ----------------
#define BB 2
#define CC 32
#define HID 16
#define K144 144
#define M4096 4096

typedef unsigned long long ull;

// ---------------- packed f32x2 helpers ----------------
__device__ __forceinline__ ull pk(float lo, float hi) {
    ull r; asm("mov.b64 %0, {%1,%2};" : "=l"(r) : "f"(lo), "f"(hi)); return r;
}
__device__ __forceinline__ ull splat(float v) { return pk(v, v); }
__device__ __forceinline__ float2 upk(ull v) {
    float2 r; asm("mov.b64 {%0,%1}, %2;" : "=f"(r.x), "=f"(r.y) : "l"(v)); return r;
}
__device__ __forceinline__ ull ffma2(ull a, ull b, ull c) {
    ull d; asm("fma.rn.f32x2 %0, %1, %2, %3;" : "=l"(d) : "l"(a), "l"(b), "l"(c)); return d;
}
__device__ __forceinline__ ull add2(ull a, ull b) {
    ull d; asm("add.rn.f32x2 %0, %1, %2;" : "=l"(d) : "l"(a), "l"(b)); return d;
}

// ---------------- device scratch ----------------
__device__ __align__(16) float2 g_S2[BB*CC*64*256];
__device__ __align__(16) float2 g_XS[BB*CC*M4096];
__device__ __align__(16) float2 g_C1P[BB*CC*8*K144];
__device__ __align__(16) float2 g_C3[BB*HID*K144];
__device__ __align__(16) float2 g_T2[BB*64*64*256];
__device__ int    g_shell[M4096];
__device__ __align__(16) float g_YW[M4096*9];
__device__ __align__(16) float g_YWT[9*M4096];
__device__ __align__(16) float g_YWsT[9*M4096];
__device__ int    g_sorted[M4096];
__device__ int    g_off[17];
__device__ float2 g_TW[64];
__device__ float2 g_WC[HID*CC];
__device__ float2 g_BC[HID];

// ---------------- K0a: mode tables + W1-fold ----------------
__global__ void k0a_init(const float* __restrict__ wfr, const float* __restrict__ wfi,
                         const float* __restrict__ bfr, const float* __restrict__ bfi,
                         const float* __restrict__ w1r, const float* __restrict__ w1i,
                         const float* __restrict__ b1r, const float* __restrict__ b1i) {
    if (blockIdx.x < 32) {
        int m = blockIdx.x * 128 + threadIdx.x;
        int ix = m >> 8, iy = (m >> 4) & 15, iz = m & 15;
        int fx = ix < 8 ? ix : ix - 16;
        int fy = iy < 8 ? iy : iy - 16;
        int fz = iz < 8 ? iz : iz - 16;
        int k2 = fx*fx + fy*fy + fz*fz;
        float rmax  = __fsqrt_rn(192.0f);
        float denom = __fadd_rn(rmax, 1e-6f);
        float r = __fsqrt_rn((float)k2);
        float q = __fmul_rn(__fdiv_rn(r, denom), 16.0f);
        int s = (int)q;
        if (s > 15) s = 15;
        g_shell[m] = s;
        float inv = (k2 > 0) ? __fdiv_rn(1.0f, r) : 0.0f;
        float ux = fx * inv, uy = fy * inv, uz = fz * inv;
        float nzm = k2 > 0 ? 1.0f : 0.0f;
        float* Y = &g_YW[m * 9];
        Y[0] = 0.282095f;
        Y[1] = 0.488603f * uy;
        Y[2] = 0.488603f * uz;
        Y[3] = 0.488603f * ux;
        Y[4] = 1.092548f * ux * uy;
        Y[5] = 1.092548f * uy * uz;
        Y[6] = 0.315392f * (3.0f * uz * uz - nzm);
        Y[7] = 1.092548f * ux * uz;
        Y[8] = 0.546274f * (ux * ux - uy * uy);
        if (blockIdx.x == 0 && threadIdx.x < 64) {
            int t = threadIdx.x;
            float ang = (float)(2.0 * M_PI * (double)t / 64.0);
            g_TW[t] = make_float2(cosf(ang), sinf(ang));
        }
    } else {
        int t = threadIdx.x;
        int jg = t >> 5, c = t & 31;
        #pragma unroll
        for (int g = 0; g < 4; g++) {
            int j = jg + g*4;
            float ar = 0.f, ai = 0.f;
            for (int o = 0; o < 32; o++) {
                float ax = w1r[j*32+o], ay = w1i[j*32+o];
                float bx = wfr[o*32+c], by = wfi[o*32+c];
                ar += ax*bx - ay*by;
                ai += ax*by + ay*bx;
            }
            g_WC[j*32+c] = make_float2(ar, ai);
            if (c == 0) {
                float br = b1r[j], bi = b1i[j];
                for (int o = 0; o < 32; o++) {
                    float ax = w1r[j*32+o], ay = w1i[j*32+o];
                    float bx = bfr[o], by = bfi[o];
                    br += ax*bx - ay*by;
                    bi += ax*by + ay*bx;
                }
                g_BC[j] = make_float2(br, bi);
            }
        }
    }
}

// ---------------- K0b ----------------
__global__ void k0b_sort() {
    int s = blockIdx.x;
    int t = threadIdx.x;                 // 256
    __shared__ int hist[16];
    __shared__ int chunkcnt[128];
    __shared__ int chunkpre[128];
    __shared__ float wSs;
    __shared__ int offs;
    if (t < 16) hist[t] = 0;
    __syncthreads();
    for (int i = t; i < M4096; i += 256) atomicAdd(&hist[g_shell[i]], 1);
    if (t < 128) {
        int c = 0;
        #pragma unroll 8
        for (int e = 0; e < 32; e++) c += (g_shell[t*32+e] == s) ? 1 : 0;
        chunkcnt[t] = c;
    }
    __syncthreads();
    if (t == 0) {
        int off = 0;
        for (int s2 = 0; s2 < s; s2++) off += hist[s2];
        offs = off;
        g_off[s] = off;
        if (s == 15) g_off[16] = off + hist[15];
        wSs = __fdiv_rn(1.0f, __fsqrt_rn(fmaxf((float)hist[s], 1.0f)));
        int acc = 0;
        for (int c = 0; c < 128; c++) { chunkpre[c] = acc; acc += chunkcnt[c]; }
    }
    __syncthreads();
    int w = t >> 5, lane = t & 31;
    float wS = wSs;
    int off0 = offs;
    for (int cc = w; cc < 128; cc += 8) {
        int m = cc*32 + lane;
        bool mine = (g_shell[m] == s);
        unsigned msk = __ballot_sync(0xffffffffu, mine);
        if (mine) {
            int p = off0 + chunkpre[cc] + __popc(msk & ((1u << lane) - 1u));
            g_sorted[p] = m;
            #pragma unroll
            for (int l = 0; l < 9; l++) {
                float v = g_YW[m*9+l] * wS;
                g_YWT[l*M4096 + m]  = v;
                g_YWsT[l*M4096 + p] = v;
            }
        }
    }
}

// ---------------- K12: forward z-DFT (double fold) + y-DFT (staged comb + LDS.128 tw) ----------------
__global__ void k12_fwd(const float* __restrict__ x) {
    __shared__ __align__(16) float xp[64*68];       // phase A input; reused for combs
    __shared__ float2 S1[1024];
    __shared__ ull twA[16*33];                      // (c,-s) for phase A
    __shared__ ulonglong2 twAB[16*33];              // {(c,-s),(s,c)} for phase B
    int blk = blockIdx.x;            // bc*64 + x
    int t = threadIdx.x;             // 256
    const float* src = x + (size_t)blk * 4096;
    #pragma unroll
    for (int it = 0; it < 4; it++) {
        int i = t + it*256;
        float4 v = *(const float4*)&src[i*4];
        int y = i >> 4, z0 = (i & 15) * 4;
        *(float4*)&xp[y*68 + z0] = v;
    }
    #pragma unroll
    for (int it = 0; it < 3; it++) {
        int i = t + it*256;
        if (i < 528) {
            int k = i / 33, j = i - k*33;
            int fk = k < 8 ? k : k - 16;
            float2 w = g_TW[(j * fk) & 63];
            ull A = pk(w.x, -w.y);
            ull B = pk(w.y, w.x);
            twA[k*33 + j] = A;
            twAB[k*33 + j] = make_ulonglong2(A, B);
        }
    }
    __syncthreads();
    // phase A: real z-DFT double fold
    {
        int y = t >> 2, q = t & 3;
        const float* row = &xp[y*68];
        float x0 = row[0], x32v = row[32];
        float sgn = (q & 1) ? -1.f : 1.f;
        ull sgnP = splat(sgn);
        ull a0 = pk(x0 + sgn*x32v, 0.f);
        ull a1 = a0;
        ull a2 = pk(x0 + x32v, 0.f);
        #pragma unroll
        for (int z = 1; z <= 15; z++) {
            float xa = row[z],      xb = row[64 - z];
            float xc = row[32 - z], xd = row[32 + z];
            float p  = xa + xb, md = xa - xb;
            float r  = xc + xd, td = xc - xd;
            ull base = pk(p, md);
            ull alt  = pk(r, -td);
            ull uvE  = add2(base, alt);
            ull uvQ  = ffma2(alt, sgnP, base);
            a2 = ffma2(uvE, twA[8*33 + z], a2);
            a0 = ffma2(uvQ, twA[q*33 + z], a0);
            a1 = ffma2(uvQ, twA[(q+4)*33 + z], a1);
        }
        {
            float xa = row[16], xb = row[48];
            ull uv16 = pk(xa + xb, xa - xb);
            a0 = ffma2(uv16, twA[q*33 + 16], a0);
            a1 = ffma2(uv16, twA[(q+4)*33 + 16], a1);
            a2 = ffma2(uv16, twA[8*33 + 16], a2);
        }
        float2 v0 = upk(a0), v1 = upk(a1), v2 = upk(a2);
        S1[y*16 + q]      = v0;
        S1[y*16 + q + 4]  = v1;
        S1[y*16 + 12 - q] = make_float2(v1.x, -v1.y);
        if (q > 0) S1[y*16 + 16 - q] = make_float2(v0.x, -v0.y);
        else       S1[y*16 + 8]      = v2;
    }
    __syncthreads();
    // stage combE/combO into xp region (phase A reads done)
    ull* cE = (ull*)xp;            // [32 y2][16 kz]
    ull* cO = cE + 512;
    {
        ull neg1 = splat(-1.f);
        #pragma unroll
        for (int it = 0; it < 2; it++) {
            int i = t + it*256;
            int y2 = i >> 4, kz = i & 15;
            ull aU = *(const ull*)&S1[y2*16 + kz];
            ull bU = *(const ull*)&S1[(y2+32)*16 + kz];
            cE[i] = add2(aU, bU);
            cO[i] = ffma2(bU, neg1, aU);
        }
    }
    __syncthreads();
    // phase B: comb (1 LDS.64) + twAB (1 LDS.128) per y2
    {
        int ky = t >> 4, kz = t & 15;
        const ull* cc = (ky & 1) ? cO : cE;
        ull acc = 0;
        #pragma unroll 8
        for (int y2 = 0; y2 < 32; y2++) {
            float2 cb = upk(cc[y2*16 + kz]);
            ulonglong2 w = twAB[ky*33 + y2];
            acc = ffma2(splat(cb.x), w.x, acc);
            acc = ffma2(splat(cb.y), w.y, acc);
        }
        g_S2[(size_t)blk * 256 + t] = upk(acc);
    }
}

// ---------------- K3: forward x-DFT with fold, LDS.128 twiddles ----------------
__global__ void k3_xdft() {
    __shared__ ulonglong2 twAB[16*33];
    int bc = blockIdx.x >> 3;
    int tq = blockIdx.x & 7;
    int tid = threadIdx.x;           // 256
    int kxg = tid >> 5, tl = tid & 31;
    int t = tq * 32 + tl;
    for (int i = tid; i < 512; i += 256) {
        int k = i >> 5, j = i & 31;
        int fk = k < 8 ? k : k - 16;
        float2 w = g_TW[(j * fk) & 63];
        twAB[k*33 + j] = make_ulonglong2(pk(w.x, -w.y), pk(w.y, w.x));
    }
    __syncthreads();
    ull acc0 = 0, acc1 = 0;
    const float2* src = g_S2 + (size_t)bc * 16384;
    ull neg1 = splat(-1.f);
    int kx0 = kxg * 2;
    #pragma unroll 4
    for (int xx = 0; xx < 32; xx++) {
        ull aU = *(const ull*)&src[xx*256 + t];
        ull bU = *(const ull*)&src[(xx+32)*256 + t];
        ull p = add2(aU, bU);
        ull mm = ffma2(bU, neg1, aU);
        float2 pp = upk(p), mv = upk(mm);
        ulonglong2 w0 = twAB[kx0*33 + xx];
        ulonglong2 w1 = twAB[(kx0+1)*33 + xx];
        acc0 = ffma2(splat(pp.x), w0.x, acc0);
        acc0 = ffma2(splat(pp.y), w0.y, acc0);
        acc1 = ffma2(splat(mv.x), w1.x, acc1);
        acc1 = ffma2(splat(mv.y), w1.y, acc1);
    }
    float2* dst = g_XS + (size_t)bc * 4096;
    dst[kx0*256 + t]     = upk(acc0);
    dst[(kx0+1)*256 + t] = upk(acc1);
}

// ---------------- K4: basis projection (smem-staged, 4-way split) ----------------
__global__ void k4_proj() {
    __shared__ __align__(16) float2 sxs[4096];
    int bc = blockIdx.x >> 2;
    int p  = blockIdx.x & 3;
    int tid = threadIdx.x;           // 256
    const float4* srcv = (const float4*)&g_XS[(size_t)bc * 4096];
    #pragma unroll
    for (int it = 0; it < 8; it++) {
        int i = tid + it*256;
        *(float4*)&sxs[i*2] = srcv[i];
    }
    __syncthreads();
    if (tid < K144) {
        int k = tid;
        int s = k / 9, l = k - s * 9;
        const float* ywp = &g_YWsT[l*M4096];
        int beg = g_off[s], end = g_off[s+1], len = end - beg;
        int i0 = beg + (len * p) / 4;
        int i1 = beg + (len * (p + 1)) / 4;
        ull acc0 = 0, acc1 = 0;
        int i = i0;
        for (; i + 2 <= i1; i += 2) {
            int m0 = g_sorted[i], m1 = g_sorted[i+1];
            float w0 = ywp[i], w1 = ywp[i+1];
            float2 u0 = sxs[m0], u1 = sxs[m1];
            acc0 = ffma2(splat(w0), pk(u0.x, u0.y), acc0);
            acc1 = ffma2(splat(w1), pk(u1.x, u1.y), acc1);
        }
        if (i < i1) {
            int m0 = g_sorted[i];
            float w0 = ywp[i];
            float2 u0 = sxs[m0];
            acc0 = ffma2(splat(w0), pk(u0.x, u0.y), acc0);
        }
        float2 a = upk(acc0), bb = upk(acc1);
        g_C1P[((size_t)bc*4 + p)*K144 + k] = make_float2(a.x + bb.x, a.y + bb.y);
    }
}

// ---------------- K5: spectral conv fused with W1 (4 partials) ----------------
__global__ void k5_conv(const float* __restrict__ wr, const float* __restrict__ wi,
                        const float* __restrict__ w1r, const float* __restrict__ w1i) {
    __shared__ float2 cin[32];
    __shared__ float2 c2s[32];
    int blk = blockIdx.x;            // b*144 + sl
    int b = blk / K144, sl = blk - b * K144;
    int o = threadIdx.x;             // 32
    {
        size_t base = ((size_t)(b*32 + o))*4*K144 + sl;
        float2 a = g_C1P[base], bb = g_C1P[base + K144];
        float2 c = g_C1P[base + 2*K144], d = g_C1P[base + 3*K144];
        cin[o] = make_float2(a.x+bb.x+c.x+d.x, a.y+bb.y+c.y+d.y);
    }
    __syncwarp();
    const float* wrp = wr + (size_t)sl * 1024 + o;
    const float* wip = wi + (size_t)sl * 1024 + o;
    float ar = 0.f, ai = 0.f;
    #pragma unroll
    for (int i = 0; i < 32; i++) {
        float2 c = cin[i];
        float a = wrp[i*32], bb = wip[i*32];
        ar += c.x*a - c.y*bb;
        ai += c.x*bb + c.y*a;
    }
    const float invn = 1.0f / 262144.0f;
    c2s[o] = make_float2(ar*invn, ai*invn);
    __syncwarp();
    if (o < HID) {
        int j = o;
        float br = 0.f, bi = 0.f;
        #pragma unroll
        for (int q = 0; q < 32; q++) {
            float ax = w1r[j*32+q], ay = w1i[j*32+q];
            float2 c = c2s[q];
            br += ax*c.x - ay*c.y;
            bi += ax*c.y + ay*c.x;
        }
        g_C3[((size_t)(b*HID + j))*K144 + sl] = make_float2(br, bi);
    }
}

// ---------------- K67: inverse basis + inverse x/y-DFT (LDS.128 twiddles) ----------------
__global__ void k67_inv() {
    __shared__ ull c3[K144];
    __shared__ ulonglong2 twiAB[16*33];   // {(c,s),(-s,c)}
    __shared__ float2 SA[256];
    __shared__ float2 SB[256];
    int bj = blockIdx.x >> 4;
    int xo = blockIdx.x & 15;
    int b = bj >> 4, j = bj & 15;
    int t = threadIdx.x;             // 256
    if (t < K144) {
        float2 v = g_C3[(size_t)bj*K144 + t];
        c3[t] = pk(v.x, v.y);
    }
    for (int i = t; i < 512; i += 256) {
        int k = i >> 5, col = i & 31;
        int fk = k < 8 ? k : k - 16;
        float2 w = g_TW[(col * fk) & 63];
        twiAB[k*33 + col] = make_ulonglong2(pk(w.x, w.y), pk(-w.y, w.x));
    }
    __syncthreads();
    ull xs2[16];
    #pragma unroll
    for (int kx = 0; kx < 16; kx++) {
        int m = (kx << 8) | t;
        int s = g_shell[m];
        ull acc = 0;
        #pragma unroll
        for (int l = 0; l < 9; l++)
            acc = ffma2(splat(g_YWT[l*M4096 + m]), c3[s*9 + l], acc);
        xs2[kx] = acc;
    }
    ull neg1 = splat(-1.f);
    int yp = t >> 3;
    int kzq = t & 7;
    #pragma unroll
    for (int xh = 0; xh < 2; xh++) {
        int xl = xo*2 + xh;
        {
            ull E = 0, O = 0;
            #pragma unroll
            for (int kx = 0; kx < 16; kx++) {
                float2 v = upk(xs2[kx]);
                ulonglong2 w = twiAB[kx*33 + xl];
                if (kx & 1) {
                    O = ffma2(splat(v.x), w.x, O);
                    O = ffma2(splat(v.y), w.y, O);
                } else {
                    E = ffma2(splat(v.x), w.x, E);
                    E = ffma2(splat(v.y), w.y, E);
                }
            }
            SA[t] = upk(add2(E, O));
            SB[t] = upk(ffma2(O, neg1, E));
        }
        __syncthreads();
        #pragma unroll
        for (int xi = 0; xi < 2; xi++) {
            const float2* S = xi ? SB : SA;
            int xx = xl + 32*xi;
            float2 r0[2], r1[2];
            #pragma unroll
            for (int k2 = 0; k2 < 2; k2++) {
                int kz = kzq*2 + k2;
                ull E = 0, O = 0;
                #pragma unroll
                for (int ky = 0; ky < 16; ky++) {
                    float2 v = S[ky*16 + kz];
                    ulonglong2 w = twiAB[ky*33 + yp];
                    if (ky & 1) {
                        O = ffma2(splat(v.x), w.x, O);
                        O = ffma2(splat(v.y), w.y, O);
                    } else {
                        E = ffma2(splat(v.x), w.x, E);
                        E = ffma2(splat(v.y), w.y, E);
                    }
                }
                r0[k2] = upk(add2(E, O));
                r1[k2] = upk(ffma2(O, neg1, E));
            }
            size_t base = ((size_t)b*64 + xx)*64;
            float4 w0 = make_float4(r0[0].x, r0[0].y, r0[1].x, r0[1].y);
            float4 w1 = make_float4(r1[0].x, r1[0].y, r1[1].x, r1[1].y);
            *(float4*)&g_T2[(base + yp)*256 + j*16 + kzq*2]      = w0;
            *(float4*)&g_T2[(base + yp + 32)*256 + j*16 + kzq*2] = w1;
        }
        __syncthreads();
    }
}

// ---------------- K8: fused epilogue, E/O z-fold via intra-warp SHFL (proven) ----------------
__device__ __forceinline__ float gelu_t(float v) {
    float u = 0.7978845608028654f * (v + 0.044715f * v * v * v);
    float e = __expf(2.0f * u);
    float th = 1.0f - 2.0f / (e + 1.0f);
    return 0.5f * v * (1.0f + th);
}

#define K8_SMEM 33280

__global__ void __launch_bounds__(128, 5)
k8_final(const float* __restrict__ x,
         const float* __restrict__ wgr,
         const float* __restrict__ w2r, const float* __restrict__ w2i,
         const float* __restrict__ b2r,
         float* __restrict__ out) {
    extern __shared__ char sm[];
    float* s_x   = (float*)sm;
    float* s_t2x = (float*)(sm + 16384);
    float* s_t2y = (float*)(sm + 18432);
    float* s_twc = (float*)(sm + 20480);
    float* s_tws = (float*)(sm + 22528);
    float* s_wcR = (float*)(sm + 24576);
    float* s_wcI = (float*)(sm + 26624);
    float* s_w2r = (float*)(sm + 28672);
    float* s_w2n = (float*)(sm + 30720);
    float* s_bcR = (float*)(sm + 32768);
    float* s_bcI = (float*)(sm + 32832);
    float* s_b2  = (float*)(sm + 32896);
    float* s_wg  = (float*)(sm + 33024);

    int blk = blockIdx.x;
    int b  = blk >> 11;
    int xc = (blk >> 5) & 63;
    int y0 = (blk & 31) * 2;
    int t = threadIdx.x;             // 128

    #pragma unroll
    for (int it = 0; it < 8; it++) {
        int i = t + it*128;
        int line = i >> 9, c = (i >> 4) & 31, zq = i & 15;
        float4 v = *(const float4*)&x[(((size_t)(b*32+c))*64 + xc)*4096 + (size_t)(y0+line)*64 + zq*4];
        *(float4*)&s_x[(line*32+c)*64 + zq*4] = v;
    }
    #pragma unroll
    for (int it = 0; it < 4; it++) {
        int i = t + it*128;
        int line = i >> 8, q = i & 255;
        int j = q >> 4, kz = q & 15;
        float2 v = g_T2[((((size_t)b*64 + xc)*64) + (y0+line))*256 + q];
        s_t2x[(line*16 + kz)*16 + j] = v.x;
        s_t2y[(line*16 + kz)*16 + j] = v.y;
    }
    #pragma unroll
    for (int it = 0; it < 4; it++) {
        int i = t + it*128;
        int kz = i >> 5, z0i = i & 31;
        int fk = kz < 8 ? kz : kz - 16;
        float2 w = g_TW[(z0i*fk) & 63];
        s_twc[i] = w.x;
        s_tws[i] = w.y;
    }
    #pragma unroll
    for (int it = 0; it < 4; it++) {
        int i = t + it*128;
        int c = i >> 4, j = i & 15;
        float2 wv = g_WC[j*32 + c];
        s_wcR[c*16 + j] = wv.x;
        s_wcI[c*16 + j] = wv.y;
        int jj = i >> 5, o = i & 31;
        s_w2r[jj*32 + o] = w2r[o*16 + jj];
        s_w2n[jj*32 + o] = -w2i[o*16 + jj];
    }
    if (t < 32) {
        s_b2[t] = b2r[t];
        s_wg[t] = wgr[t];
        if (t < 16) { float2 v = g_BC[t]; s_bcR[t] = v.x; s_bcI[t] = v.y; }
    }
    __syncthreads();

    int line = t >> 6;
    int zh   = t & 63;
    int isO  = (zh >> 4) & 1;
    int z0   = (zh & 15) | ((zh >> 5) << 4);
    int myz  = z0 + (isO << 5);
    const float* xl = &s_x[line*2048];

    ull accR[8] = {0,0,0,0,0,0,0,0}, accI[8] = {0,0,0,0,0,0,0,0};
    #pragma unroll
    for (int kk = 0; kk < 8; kk++) {
        int kz = kk*2 + isO;
        float cw = s_twc[kz*32 + z0], sw = s_tws[kz*32 + z0];
        ull sc = splat(cw), ss = splat(sw), sn = splat(-sw);
        const ulonglong2* tx = (const ulonglong2*)&s_t2x[(line*16 + kz)*16];
        const ulonglong2* ty = (const ulonglong2*)&s_t2y[(line*16 + kz)*16];
        #pragma unroll
        for (int p = 0; p < 4; p++) {
            ulonglong2 a = tx[p], bv = ty[p];
            accR[2*p]   = ffma2(a.x,  sc, accR[2*p]);
            accR[2*p]   = ffma2(bv.x, sn, accR[2*p]);
            accI[2*p]   = ffma2(a.x,  ss, accI[2*p]);
            accI[2*p]   = ffma2(bv.x, sc, accI[2*p]);
            accR[2*p+1] = ffma2(a.y,  sc, accR[2*p+1]);
            accR[2*p+1] = ffma2(bv.y, sn, accR[2*p+1]);
            accI[2*p+1] = ffma2(a.y,  ss, accI[2*p+1]);
            accI[2*p+1] = ffma2(bv.y, sc, accI[2*p+1]);
        }
    }
    {
        ull sgnU = splat(isO ? -1.f : 1.f);
        #pragma unroll
        for (int jp = 0; jp < 8; jp++) {
            ull oR = __shfl_xor_sync(0xffffffffu, accR[jp], 16);
            ull oI = __shfl_xor_sync(0xffffffffu, accI[jp], 16);
            accR[jp] = ffma2(accR[jp], sgnU, add2(oR, *(const ull*)&s_bcR[jp*2]));
            accI[jp] = ffma2(accI[jp], sgnU, add2(oI, *(const ull*)&s_bcI[jp*2]));
        }
    }

    #pragma unroll 4
    for (int c = 0; c < 32; c++) {
        ull sx = splat(xl[c*64 + myz]);
        const ulonglong2* wr = (const ulonglong2*)&s_wcR[c*16];
        const ulonglong2* wi = (const ulonglong2*)&s_wcI[c*16];
        #pragma unroll
        for (int p = 0; p < 4; p++) {
            ulonglong2 a = wr[p], bv = wi[p];
            accR[2*p]   = ffma2(a.x,  sx, accR[2*p]);
            accR[2*p+1] = ffma2(a.y,  sx, accR[2*p+1]);
            accI[2*p]   = ffma2(bv.x, sx, accI[2*p]);
            accI[2*p+1] = ffma2(bv.y, sx, accI[2*p+1]);
        }
    }

    float hrf[16], hif[16];
    #pragma unroll
    for (int jp = 0; jp < 8; jp++) {
        float2 r  = upk(accR[jp]);
        float2 im = upk(accI[jp]);
        hrf[2*jp]   = gelu_t(r.x);
        hrf[2*jp+1] = gelu_t(r.y);
        hif[2*jp]   = gelu_t(im.x);
        hif[2*jp+1] = gelu_t(im.y);
    }

    int y = y0 + line;
    size_t obase = (((size_t)(b*32))*64 + xc)*4096 + (size_t)y*64 + myz;
    #pragma unroll
    for (int h = 0; h < 2; h++) {
        ull accO[8];
        #pragma unroll
        for (int op = 0; op < 8; op++) {
            int o = h*16 + op*2;
            ull b2p = *(const ull*)&s_b2[o];
            ull wgp = *(const ull*)&s_wg[o];
            ull xp  = pk(xl[o*64 + myz], xl[(o+1)*64 + myz]);
            accO[op] = ffma2(xp, wgp, b2p);
        }
        #pragma unroll
        for (int j = 0; j < 16; j++) {
            ull shr = splat(hrf[j]), shi = splat(hif[j]);
            const ulonglong2* wr = (const ulonglong2*)&s_w2r[j*32 + h*16];
            const ulonglong2* wn = (const ulonglong2*)&s_w2n[j*32 + h*16];
            #pragma unroll
            for (int p = 0; p < 4; p++) {
                ulonglong2 a = wr[p], bv = wn[p];
                accO[2*p]   = ffma2(a.x,  shr, accO[2*p]);
                accO[2*p]   = ffma2(bv.x, shi, accO[2*p]);
                accO[2*p+1] = ffma2(a.y,  shr, accO[2*p+1]);
                accO[2*p+1] = ffma2(bv.y, shi, accO[2*p+1]);
            }
        }
        #pragma unroll
        for (int op = 0; op < 8; op++) {
            int o = h*16 + op*2;
            float2 v = upk(accO[op]);
            out[obase + (size_t)o     * 262144] = v.x;
            out[obase + (size_t)(o+1) * 262144] = v.y;
        }
    }
}

// ---------------- launch ----------------
extern "C" void kernel_launch(void* const* d_in, const int* in_sizes, int n_in,
                              void* d_out, int out_size) {
    const float* x    = (const float*)d_in[0];
    const float* wfr  = (const float*)d_in[1];
    const float* wfi  = (const float*)d_in[2];
    const float* bfr  = (const float*)d_in[3];
    const float* bfi  = (const float*)d_in[4];
    const float* wgr  = (const float*)d_in[5];
    const float* wsr  = (const float*)d_in[7];
    const float* wsi  = (const float*)d_in[8];
    const float* w1r  = (const float*)d_in[9];
    const float* w1i  = (const float*)d_in[10];
    const float* b1r  = (const float*)d_in[11];
    const float* b1i  = (const float*)d_in[12];
    const float* w2r  = (const float*)d_in[13];
    const float* w2i  = (const float*)d_in[14];
    const float* b2r  = (const float*)d_in[15];
    float* out = (float*)d_out;

    cudaFuncSetAttribute(k8_final, cudaFuncAttributeMaxDynamicSharedMemorySize, K8_SMEM);

    k0a_init<<<33, 128>>>(wfr, wfi, bfr, bfi, w1r, w1i, b1r, b1i);
    k0b_sort<<<16, 256>>>();
    k12_fwd<<<BB*CC*64, 256>>>(x);
    k3_xdft<<<BB*CC*8, 256>>>();
    k4_proj<<<BB*CC*4, 256>>>();
    k5_conv<<<BB*K144, 32>>>(wsr, wsi, w1r, w1i);
    k67_inv<<<BB*HID*16, 256>>>();
    k8_final<<<BB*64*32, 128, K8_SMEM>>>(x, wgr, w2r, w2i, b2r, out);
}